// round 8
// baseline (speedup 1.0000x reference)
#include <cuda_runtime.h>
#include <cstdint>
#include <cstddef>

#define BS      64
#define NVAL    25200
#define KCAND   512
#define MAXDET  300
#define CONF_T  0.25f
#define IOU_T   0.45f
#define MAX_WH  7680.0f
#define NBIN    4096
#define CAP     6144

typedef unsigned long long u64;

// ---- static device scratch (no allocation anywhere) ----
__device__ u64          g_keys[(size_t)BS * NVAL];        // 12.9 MB
__device__ unsigned int g_hist[BS][NBIN];                 // 1 MB; zero-init; self-resetting
__device__ float        g_ox1[BS * KCAND], g_oy1[BS * KCAND];
__device__ float        g_ox2[BS * KCAND], g_oy2[BS * KCAND];
__device__ float        g_area[BS * KCAND], g_score[BS * KCAND];
__device__ int          g_cid[BS * KCAND], g_topi[BS * KCAND];
__device__ u64          g_tmask[(size_t)BS * 8 * KCAND];  // 2 MB, word-major

// ---------------------------------------------------------------------------
// K1: scores -> 64-bit sortable keys + per-image 4096-bin histogram on the
//     top 12 key bits. Warp-aggregated atomics.
// ---------------------------------------------------------------------------
__global__ void score_kernel(const float* __restrict__ pred) {
    int b = blockIdx.y;
    int i = blockIdx.x * blockDim.x + threadIdx.x;
    __shared__ unsigned int sh[NBIN];
    #pragma unroll
    for (int t = threadIdx.x; t < NBIN; t += 1024) sh[t] = 0u;
    __syncthreads();

    bool act = (i < NVAL);
    unsigned int am = __ballot_sync(0xffffffffu, act);
    if (act) {
        const float4* p = (const float4*)(pred + ((size_t)b * NVAL + i) * 8);
        float4 c = p[1];                           // obj, cls0, cls1, cls2
        float s0 = __fmul_rn(c.x, c.y);
        float s1 = __fmul_rn(c.x, c.z);
        float s2 = __fmul_rn(c.x, c.w);
        float best = s0;
        if (s1 > best) best = s1;
        if (s2 > best) best = s2;
        unsigned int bits = __float_as_uint(best); // scores >= 0 -> monotonic
        g_keys[(size_t)b * NVAL + i] =
            ((u64)bits << 32) | (0xFFFFFFFFu - (unsigned int)i);
        unsigned int bin = bits >> 20;             // 12-bit MSB digit
        unsigned int mm = __match_any_sync(am, bin);
        if ((threadIdx.x & 31) == (__ffs(mm) - 1))
            atomicAdd(&sh[bin], (unsigned int)__popc(mm));
    }
    __syncthreads();
    #pragma unroll
    for (int t = threadIdx.x; t < NBIN; t += 1024)
        if (sh[t]) atomicAdd(&g_hist[b][t], sh[t]);
}

// ---------------------------------------------------------------------------
// K2: exact top-512 via 12-bit pre-hist + single global pass + smem-buffer
//     radix tail + bitonic sort. One block / image, 1024 threads.
// Dynamic smem: buf[CAP] u64 | keysS[512] u64 | h4k[4096] u32  = 69632 B
// ---------------------------------------------------------------------------
extern __shared__ unsigned char smdyn[];

__global__ void __launch_bounds__(1024, 1)
select_kernel(const float* __restrict__ pred) {
    const int b   = blockIdx.x;
    const int tid = threadIdx.x;

    u64*          buf   = (u64*)(smdyn);                       // CAP*8 = 49152
    u64*          keysS = (u64*)(smdyn + CAP * 8);             // 4096
    unsigned int* h4k   = (unsigned int*)(smdyn + CAP * 8 + 4096); // 16384

    __shared__ unsigned int Tarr[1024];
    __shared__ unsigned int hist[257];
    __shared__ u64 s_pf;
    __shared__ int s_shift, s_done, s_need;
    __shared__ unsigned int s_cntS, s_cntB;
    __shared__ int s_b12;

    const u64* keys = g_keys + (size_t)b * NVAL;

    // ---- load 4096-bin hist (4/thread), reset global copy ----
    unsigned int h0, h1, h2, h3;
    {
        int base = tid * 4;
        h0 = g_hist[b][base];     g_hist[b][base]     = 0u;
        h1 = g_hist[b][base + 1]; g_hist[b][base + 1] = 0u;
        h2 = g_hist[b][base + 2]; g_hist[b][base + 2] = 0u;
        h3 = g_hist[b][base + 3]; g_hist[b][base + 3] = 0u;
    }
    // local suffixes within this thread's 4 bins
    unsigned int l3 = h3, l2 = h2 + l3, l1 = h1 + l2, l0 = h0 + l1;
    Tarr[tid] = l0;
    if (tid == 0) { s_done = 0; s_cntS = 0u; s_cntB = 0u; }
    __syncthreads();
    // suffix scan over 1024 thread-totals
    #pragma unroll
    for (int off = 1; off < 1024; off <<= 1) {
        unsigned int v = Tarr[tid] + ((tid + off < 1024) ? Tarr[tid + off] : 0u);
        __syncthreads();
        Tarr[tid] = v;
        __syncthreads();
    }
    {
        unsigned int base = (tid < 1023) ? Tarr[tid + 1] : 0u;
        unsigned int sfx[5];
        sfx[0] = l0 + base; sfx[1] = l1 + base; sfx[2] = l2 + base;
        sfx[3] = l3 + base; sfx[4] = base;
        unsigned int hh[4] = {h0, h1, h2, h3};
        #pragma unroll
        for (int k = 0; k < 4; ++k) {
            if ((int)sfx[k] >= KCAND && (int)sfx[k + 1] < KCAND) {  // unique crossing
                int need_new = KCAND - (int)sfx[k + 1];
                s_b12  = tid * 4 + k;
                s_pf   = (u64)(tid * 4 + k);
                s_shift = 52;
                s_need  = need_new;
                if ((int)hh[k] == need_new) s_done = 1;
            }
        }
    }
    __syncthreads();

    // ---- single global pass: sure-winners -> keysS, threshold bin -> buf ----
    {
        const unsigned int b12 = (unsigned int)s_b12;
        for (int i = tid; i < NVAL; i += 1024) {
            u64 kk = keys[i];
            unsigned int d = (unsigned int)(kk >> 52);
            if (d > b12) {
                keysS[atomicAdd(&s_cntS, 1u)] = kk;
            } else if (d == b12) {
                unsigned int p2 = atomicAdd(&s_cntB, 1u);
                if (p2 < CAP) buf[p2] = kk;
            }
        }
    }
    __syncthreads();
    const bool overflow = (s_cntB > CAP);
    const int  nbuf     = overflow ? 0 : (int)s_cntB;
    const unsigned int b12v = (unsigned int)s_b12;

    // ---- deeper radix levels on the smem buffer (or global on overflow) ----
    for (int lvl = 0; lvl < 7 && !s_done; ++lvl) {
        u64 pf    = s_pf;
        int shift = s_shift;
        int w     = (shift >= 8) ? 8 : shift;
        int nsh   = shift - w;
        if (tid < 257) hist[tid] = 0u;
        __syncthreads();
        if (!overflow) {
            for (int i = tid; i < nbuf; i += 1024) {
                u64 kk = buf[i];
                if ((kk >> shift) == pf)
                    atomicAdd(&hist[(unsigned int)(kk >> nsh) & ((1u << w) - 1u)], 1u);
            }
        } else {
            for (int i = tid; i < NVAL; i += 1024) {
                u64 kk = keys[i];
                if ((kk >> shift) == pf)
                    atomicAdd(&hist[(unsigned int)(kk >> nsh) & ((1u << w) - 1u)], 1u);
            }
        }
        __syncthreads();
        // parallel suffix over 256
        #pragma unroll
        for (int off = 1; off < 256; off <<= 1) {
            unsigned int v = 0;
            if (tid < 256)
                v = hist[tid] + ((tid + off < 256) ? hist[tid + off] : 0u);
            __syncthreads();
            if (tid < 256) hist[tid] = v;
            __syncthreads();
        }
        const int need = s_need;      // snapshot in ALL threads
        __syncthreads();
        if (tid < 256) {
            unsigned int sfx = hist[tid], sfx1 = hist[tid + 1];
            if ((int)sfx >= need && (int)sfx1 < need) {
                int hbin     = (int)(sfx - sfx1);
                int need_new = need - (int)sfx1;
                s_pf    = (pf << w) | (unsigned int)tid;
                s_shift = nsh;
                s_need  = need_new;
                if (hbin == need_new || nsh == 0) s_done = 1;
            }
        }
        __syncthreads();
    }

    // ---- final compact: remaining winners from buffer (or global) ----
    {
        u64 pf    = s_pf;
        int shift = s_shift;
        if (!overflow) {
            for (int i = tid; i < nbuf; i += 1024) {
                u64 kk = buf[i];
                if ((kk >> shift) >= pf)
                    keysS[atomicAdd(&s_cntS, 1u)] = kk;
            }
        } else {
            for (int i = tid; i < NVAL; i += 1024) {
                u64 kk = keys[i];
                if (((unsigned int)(kk >> 52) == b12v) && ((kk >> shift) >= pf))
                    keysS[atomicAdd(&s_cntS, 1u)] = kk;
            }
        }
    }
    __syncthreads();

    // ---- bitonic sort descending (512 distinct keys -> deterministic) ----
    for (int kk = 2; kk <= KCAND; kk <<= 1) {
        for (int j = kk >> 1; j > 0; j >>= 1) {
            if (tid < KCAND) {
                int ixj = tid ^ j;
                if (ixj > tid) {
                    bool dirDesc = ((tid & kk) == 0);
                    u64 a = keysS[tid], c = keysS[ixj];
                    bool sw = dirDesc ? (a < c) : (a > c);
                    if (sw) { keysS[tid] = c; keysS[ixj] = a; }
                }
            }
            __syncthreads();
        }
    }

    // ---- extract candidate data -> global ----
    if (tid < KCAND) {
        u64 kk = keysS[tid];
        int   idx = (int)(0xFFFFFFFFu - (unsigned int)kk);
        float sc  = __uint_as_float((unsigned int)(kk >> 32));
        const float4* p = (const float4*)(pred + ((size_t)b * NVAL + idx) * 8);
        float4 a = p[0];                 // cx, cy, w, h
        float4 c = p[1];                 // obj, cls0..2
        float s0 = __fmul_rn(c.x, c.y);
        float s1 = __fmul_rn(c.x, c.z);
        float s2 = __fmul_rn(c.x, c.w);
        int cid = 0; float bv = s0;
        if (s1 > bv) { bv = s1; cid = 1; }
        if (s2 > bv) { bv = s2; cid = 2; }
        float hw  = __fmul_rn(a.z, 0.5f), hh = __fmul_rn(a.w, 0.5f);
        float bx1 = __fsub_rn(a.x, hw),  by1 = __fsub_rn(a.y, hh);
        float bx2 = __fadd_rn(a.x, hw),  by2 = __fadd_rn(a.y, hh);
        float off = __fmul_rn((float)cid, MAX_WH);
        float X1 = __fadd_rn(bx1, off), Y1 = __fadd_rn(by1, off);
        float X2 = __fadd_rn(bx2, off), Y2 = __fadd_rn(by2, off);
        int g = b * KCAND + tid;
        g_ox1[g] = X1; g_oy1[g] = Y1; g_ox2[g] = X2; g_oy2[g] = Y2;
        g_area[g]  = __fmul_rn(__fsub_rn(X2, X1), __fsub_rn(Y2, Y1));
        g_score[g] = sc;
        g_cid[g]   = cid;
        g_topi[g]  = idx;
    }
}

// ---------------------------------------------------------------------------
// K3: suppression mask, chip-wide. grid=(8 row-chunks, BS), 512 threads.
// ---------------------------------------------------------------------------
__global__ void __launch_bounds__(512)
mask_kernel() {
    const int b   = blockIdx.y;
    const int ic  = blockIdx.x;            // row chunk
    const int tid = threadIdx.x;

    __shared__ float sx1[KCAND], sy1[KCAND], sx2[KCAND], sy2[KCAND], sar[KCAND];
    {
        int g = b * KCAND + tid;
        sx1[tid] = g_ox1[g]; sy1[tid] = g_oy1[g];
        sx2[tid] = g_ox2[g]; sy2[tid] = g_oy2[g];
        sar[tid] = g_area[g];
    }
    __syncthreads();

    const int w  = tid >> 6;               // j-word 0..7
    const int li = tid & 63;
    const int i  = (ic << 6) + li;         // row
    u64 word = 0ull;
    if (w >= ic) {                         // below-diagonal words are all zero
        float ax1 = sx1[i], ay1 = sy1[i], ax2 = sx2[i], ay2 = sy2[i], aa = sar[i];
        int jbase = w << 6;
        #pragma unroll 4
        for (int bb = 0; bb < 64; ++bb) {
            int j = jbase + bb;
            float ltx = fmaxf(ax1, sx1[j]), lty = fmaxf(ay1, sy1[j]);
            float rbx = fminf(ax2, sx2[j]), rby = fminf(ay2, sy2[j]);
            float iw = fmaxf(__fsub_rn(rbx, ltx), 0.0f);
            float ih = fmaxf(__fsub_rn(rby, lty), 0.0f);
            float inter = __fmul_rn(iw, ih);
            if ((j > i) && (inter > 0.0f)) {   // inter==0 -> iou==0 exactly
                float denom = __fadd_rn(__fsub_rn(__fadd_rn(aa, sar[j]), inter), 1e-7f);
                if (__fdiv_rn(inter, denom) > IOU_T) word |= (1ull << bb);
            }
        }
    }
    g_tmask[((size_t)b * 8 + w) * KCAND + i] = word;   // coalesced
}

// ---------------------------------------------------------------------------
// K4: sparsity-aware greedy scan + parallel pack. One block / image.
// ---------------------------------------------------------------------------
__global__ void __launch_bounds__(1024, 1)
final_kernel(const float* __restrict__ pred, float* __restrict__ out) {
    const int b   = blockIdx.x;
    const int tid = threadIdx.x;

    __shared__ u64 tm[KCAND * 8];              // 32 KB, word-major
    __shared__ unsigned int nz32[16], conf32[16], valid32[16];
    __shared__ int s_nv;

    {
        const u64* gm = g_tmask + (size_t)b * KCAND * 8;
        #pragma unroll
        for (int t = tid; t < KCAND * 8; t += 1024) tm[t] = gm[t];
    }
    __syncthreads();

    if (tid < KCAND) {
        u64 o = tm[tid]            | tm[KCAND     + tid] |
                tm[2*KCAND + tid]  | tm[3*KCAND   + tid] |
                tm[4*KCAND + tid]  | tm[5*KCAND   + tid] |
                tm[6*KCAND + tid]  | tm[7*KCAND   + tid];
        unsigned bnz = __ballot_sync(0xffffffffu, o != 0ull);
        unsigned bcf = __ballot_sync(0xffffffffu, g_score[b * KCAND + tid] > CONF_T);
        if ((tid & 31) == 0) { nz32[tid >> 5] = bnz; conf32[tid >> 5] = bcf; }
    }
    __syncthreads();

    if (tid == 0) {
        u64 sup[8] = {0,0,0,0,0,0,0,0};
        u64 nz[8];
        #pragma unroll
        for (int q = 0; q < 8; ++q)
            nz[q] = (u64)nz32[2*q] | ((u64)nz32[2*q + 1] << 32);
        #pragma unroll
        for (int w = 0; w < 8; ++w) {
            u64 x = nz[w] & ~sup[w];
            while (x) {
                int bb = __ffsll((long long)x) - 1;
                int i = (w << 6) + bb;
                #pragma unroll
                for (int q = 0; q < 8; ++q) sup[q] |= tm[q * KCAND + i];
                u64 above = (bb == 63) ? 0ull : (~0ull << (bb + 1));
                x = nz[w] & ~sup[w] & above;
            }
        }
        int nv = 0;
        #pragma unroll
        for (int w = 0; w < 8; ++w) {
            u64 conf = (u64)conf32[2*w] | ((u64)conf32[2*w + 1] << 32);
            u64 valid = (~sup[w]) & conf;
            if (w == 0) valid |= 1ull;     // index 0: never suppressed, rank 1
            valid32[2*w]     = (unsigned int)valid;
            valid32[2*w + 1] = (unsigned int)(valid >> 32);
            nv += __popcll(valid);
        }
        s_nv = nv;
    }
    __syncthreads();

    if (tid < MAXDET) {
        int nv = s_nv;
        bool isv = tid < nv;
        int r = isv ? tid : tid - nv;
        int k = -1;
        #pragma unroll
        for (int wi = 0; wi < 16; ++wi) {
            unsigned wv = valid32[wi];
            if (!isv) wv = ~wv;
            int c = __popc(wv);
            if (k < 0) {
                if (r < c) k = wi * 32 + __fns(wv, 0, r + 1);
                else       r -= c;
            }
        }
        int g  = b * KCAND + k;
        int gi = g_topi[g];
        float b0 = 0.f, b1 = 0.f, b2 = 0.f, b3 = 0.f, sc = 0.f;
        if (isv) {
            const float4* p = (const float4*)(pred + ((size_t)b * NVAL + gi) * 8);
            float4 a = p[0];
            float hw = __fmul_rn(a.z, 0.5f), hh = __fmul_rn(a.w, 0.5f);
            b0 = __fsub_rn(a.x, hw); b1 = __fsub_rn(a.y, hh);
            b2 = __fadd_rn(a.x, hw); b3 = __fadd_rn(a.y, hh);
            sc = g_score[g];
        }
        const size_t scoresOff = (size_t)BS * MAXDET * 4;
        const size_t clsOff    = scoresOff + (size_t)BS * MAXDET;
        const size_t idsOff    = clsOff    + (size_t)BS * MAXDET;
        const size_t valOff    = idsOff    + (size_t)BS * MAXDET;
        size_t rr = (size_t)b * MAXDET + tid;
        out[rr * 4 + 0] = b0;
        out[rr * 4 + 1] = b1;
        out[rr * 4 + 2] = b2;
        out[rr * 4 + 3] = b3;
        out[scoresOff + rr] = sc;
        out[clsOff + rr] = (float)g_cid[g];    // NOT zeroed for pads (ref semantics)
        out[idsOff + rr] = (float)(gi / 3);    // NOT zeroed for pads (ref semantics)
        out[valOff + rr] = isv ? 1.0f : 0.0f;
    }
}

// ---------------------------------------------------------------------------
extern "C" void kernel_launch(void* const* d_in, const int* in_sizes, int n_in,
                              void* d_out, int out_size) {
    (void)in_sizes; (void)n_in; (void)out_size;
    const float* pred = (const float*)d_in[0];
    float* out = (float*)d_out;

    score_kernel<<<dim3((NVAL + 1023) / 1024, BS), 1024>>>(pred);
    cudaFuncSetAttribute(select_kernel,
                         cudaFuncAttributeMaxDynamicSharedMemorySize, 69632);
    select_kernel<<<BS, 1024, 69632>>>(pred);
    mask_kernel<<<dim3(8, BS), 512>>>();
    final_kernel<<<BS, 1024>>>(pred, out);
}